// round 1
// baseline (speedup 1.0000x reference)
#include <cuda_runtime.h>

#define T_SEQ 4096
#define C_DIM 1024
#define NH    16
#define DHEAD 64
#define BANDW 128

// Scratch (allocation-free rule: __device__ globals)
__device__ float g_q[T_SEQ * C_DIM];
__device__ float g_k[T_SEQ * C_DIM];
__device__ float g_v[T_SEQ * C_DIM];
__device__ float g_att[T_SEQ * C_DIM];

// ----------------------------------------------------------------------------
// C[M,N] = A[M,K] @ B[N,K]^T   (row-major; M,N multiples of 128, K multiple of 8)
// 128x128 block tile, BK=8, 256 threads, 8x8 microtile.
// ----------------------------------------------------------------------------
__global__ __launch_bounds__(256) void sgemm_abt(const float* __restrict__ A,
                                                 const float* __restrict__ B,
                                                 float* __restrict__ C,
                                                 int M, int N, int K) {
    __shared__ float As[8][128];
    __shared__ float Bs[8][128];

    const int tid = threadIdx.x;
    const int m0 = blockIdx.y * 128;
    const int n0 = blockIdx.x * 128;
    const int tx = tid & 15;        // 0..15
    const int ty = tid >> 4;        // 0..15
    const int lr = tid >> 1;        // 0..127 (tile row for loads)
    const int lc = (tid & 1) * 4;   // 0 or 4

    float acc[8][8];
#pragma unroll
    for (int i = 0; i < 8; i++)
#pragma unroll
        for (int j = 0; j < 8; j++) acc[i][j] = 0.0f;

    const float* Ap = A + (size_t)(m0 + lr) * K + lc;
    const float* Bp = B + (size_t)(n0 + lr) * K + lc;

    for (int k0 = 0; k0 < K; k0 += 8) {
        float4 a = *(const float4*)(Ap + k0);
        float4 b = *(const float4*)(Bp + k0);
        As[lc + 0][lr] = a.x; As[lc + 1][lr] = a.y;
        As[lc + 2][lr] = a.z; As[lc + 3][lr] = a.w;
        Bs[lc + 0][lr] = b.x; Bs[lc + 1][lr] = b.y;
        Bs[lc + 2][lr] = b.z; Bs[lc + 3][lr] = b.w;
        __syncthreads();

#pragma unroll
        for (int kk = 0; kk < 8; kk++) {
            float4 a0 = *(const float4*)&As[kk][ty * 8];
            float4 a1 = *(const float4*)&As[kk][ty * 8 + 4];
            float4 b0 = *(const float4*)&Bs[kk][tx * 8];
            float4 b1 = *(const float4*)&Bs[kk][tx * 8 + 4];
            float ar[8] = {a0.x, a0.y, a0.z, a0.w, a1.x, a1.y, a1.z, a1.w};
            float br[8] = {b0.x, b0.y, b0.z, b0.w, b1.x, b1.y, b1.z, b1.w};
#pragma unroll
            for (int i = 0; i < 8; i++)
#pragma unroll
                for (int j = 0; j < 8; j++)
                    acc[i][j] = fmaf(ar[i], br[j], acc[i][j]);
        }
        __syncthreads();
    }

#pragma unroll
    for (int i = 0; i < 8; i++) {
        int m = m0 + ty * 8 + i;
        float* Crow = C + (size_t)m * N + n0 + tx * 8;
#pragma unroll
        for (int j = 0; j < 8; j += 4) {
            float4 o = make_float4(acc[i][j], acc[i][j + 1], acc[i][j + 2], acc[i][j + 3]);
            *(float4*)(Crow + j) = o;
        }
    }
}

// ----------------------------------------------------------------------------
// Banded causal attention.
// Block = (64-query tile, head). Window for queries [t0, t0+63] is keys
// [t0-128+1, t0+63]; we stage 192 key rows starting at t0-128 (row 0 is
// always masked out, rows with jg<0 are zero-filled and masked).
// 256 threads: 4 lanes per query row; lane handles keys j = sub + 4n.
// ----------------------------------------------------------------------------
#define QT 64
#define KT 192
#define ATTN_SMEM ((QT + 2 * KT) * DHEAD * sizeof(float))  // 114688 B

__global__ __launch_bounds__(256, 1) void attn_kernel(const float* __restrict__ q,
                                                      const float* __restrict__ k,
                                                      const float* __restrict__ v,
                                                      float* __restrict__ y) {
    extern __shared__ float sh[];
    float* Qs = sh;                 // [QT][64]
    float* Ks = sh + QT * DHEAD;    // [KT][64]
    float* Vs = Ks + KT * DHEAD;    // [KT][64]

    const int h  = blockIdx.y;
    const int t0 = blockIdx.x * QT;
    const int tid = threadIdx.x;
    const int hoff = h * DHEAD;

    // load Q tile (QT*16 float4s)
    for (int idx = tid; idx < QT * 16; idx += 256) {
        int row = idx >> 4;
        int c4  = (idx & 15) * 4;
        ((float4*)Qs)[idx] = *(const float4*)&q[(size_t)(t0 + row) * C_DIM + hoff + c4];
    }
    // load K/V tiles (KT*16 float4s each); jg<0 rows zero-filled
    for (int idx = tid; idx < KT * 16; idx += 256) {
        int row = idx >> 4;
        int c4  = (idx & 15) * 4;
        int jg  = t0 - BANDW + row;
        float4 kv = make_float4(0.f, 0.f, 0.f, 0.f);
        float4 vv = make_float4(0.f, 0.f, 0.f, 0.f);
        if (jg >= 0) {
            kv = *(const float4*)&k[(size_t)jg * C_DIM + hoff + c4];
            vv = *(const float4*)&v[(size_t)jg * C_DIM + hoff + c4];
        }
        ((float4*)Ks)[idx] = kv;
        ((float4*)Vs)[idx] = vv;
    }
    __syncthreads();

    const int qi  = tid >> 2;   // 0..63
    const int sub = tid & 3;    // 0..3
    const int i   = t0 + qi;    // global query index

    // q row into registers
    float4 qr[16];
#pragma unroll
    for (int c = 0; c < 16; c++) qr[c] = ((const float4*)(Qs + qi * DHEAD))[c];

    // scores for keys j = sub + 4n
    float s[48];
    float mx = -1e30f;
#pragma unroll
    for (int n = 0; n < 48; n++) {
        int j  = sub + 4 * n;
        int jg = t0 - BANDW + j;
        const float4* kr = (const float4*)(Ks + j * DHEAD);
        float d = 0.0f;
#pragma unroll
        for (int c = 0; c < 16; c++) {
            float4 kk = kr[c];
            d = fmaf(qr[c].x, kk.x, d);
            d = fmaf(qr[c].y, kk.y, d);
            d = fmaf(qr[c].z, kk.z, d);
            d = fmaf(qr[c].w, kk.w, d);
        }
        bool valid = (jg >= 0) && (jg <= i) && ((i - jg) < BANDW);
        s[n] = valid ? d * 0.125f : -1e30f;   // 1/sqrt(64)
        mx = fmaxf(mx, s[n]);
    }
    // row max across the 4 lanes owning this query
    mx = fmaxf(mx, __shfl_xor_sync(0xFFFFFFFFu, mx, 1));
    mx = fmaxf(mx, __shfl_xor_sync(0xFFFFFFFFu, mx, 2));

    float sum = 0.0f;
#pragma unroll
    for (int n = 0; n < 48; n++) {
        s[n] = __expf(s[n] - mx);   // masked -> exp(~-1e30) == 0
        sum += s[n];
    }
    sum += __shfl_xor_sync(0xFFFFFFFFu, sum, 1);
    sum += __shfl_xor_sync(0xFFFFFFFFu, sum, 2);
    float inv = 1.0f / sum;

    // P @ V (unnormalized), reduce across lanes, normalize at write
    float acc[DHEAD];
#pragma unroll
    for (int c = 0; c < DHEAD; c++) acc[c] = 0.0f;

#pragma unroll
    for (int n = 0; n < 48; n++) {
        int j = sub + 4 * n;
        float p = s[n];
        const float4* vr = (const float4*)(Vs + j * DHEAD);
#pragma unroll
        for (int c = 0; c < 16; c++) {
            float4 vv = vr[c];
            acc[4 * c + 0] = fmaf(p, vv.x, acc[4 * c + 0]);
            acc[4 * c + 1] = fmaf(p, vv.y, acc[4 * c + 1]);
            acc[4 * c + 2] = fmaf(p, vv.z, acc[4 * c + 2]);
            acc[4 * c + 3] = fmaf(p, vv.w, acc[4 * c + 3]);
        }
    }
#pragma unroll
    for (int c = 0; c < DHEAD; c++) {
        acc[c] += __shfl_xor_sync(0xFFFFFFFFu, acc[c], 1);
        acc[c] += __shfl_xor_sync(0xFFFFFFFFu, acc[c], 2);
    }

    // each lane writes its 16 of the 64 dims
#pragma unroll
    for (int c4 = 0; c4 < 4; c4++) {
        int c = sub * 16 + c4 * 4;
        float4 o = make_float4(acc[c] * inv, acc[c + 1] * inv,
                               acc[c + 2] * inv, acc[c + 3] * inv);
        *(float4*)&y[(size_t)i * C_DIM + hoff + c] = o;
    }
}

// ----------------------------------------------------------------------------
extern "C" void kernel_launch(void* const* d_in, const int* in_sizes, int n_in,
                              void* d_out, int out_size) {
    const float* x  = (const float*)d_in[0];
    const float* Wq = (const float*)d_in[1];
    const float* Wk = (const float*)d_in[2];
    const float* Wv = (const float*)d_in[3];
    const float* Wo = (const float*)d_in[4];
    float* out = (float*)d_out;

    float *qp, *kp, *vp, *ap;
    cudaGetSymbolAddress((void**)&qp, g_q);
    cudaGetSymbolAddress((void**)&kp, g_k);
    cudaGetSymbolAddress((void**)&vp, g_v);
    cudaGetSymbolAddress((void**)&ap, g_att);

    cudaFuncSetAttribute(attn_kernel, cudaFuncAttributeMaxDynamicSharedMemorySize,
                         (int)ATTN_SMEM);

    dim3 gg(C_DIM / 128, T_SEQ / 128);
    sgemm_abt<<<gg, 256>>>(x, Wq, qp, T_SEQ, C_DIM, C_DIM);
    sgemm_abt<<<gg, 256>>>(x, Wk, kp, T_SEQ, C_DIM, C_DIM);
    sgemm_abt<<<gg, 256>>>(x, Wv, vp, T_SEQ, C_DIM, C_DIM);

    attn_kernel<<<dim3(T_SEQ / QT, NH), 256, ATTN_SMEM>>>(qp, kp, vp, ap);

    sgemm_abt<<<gg, 256>>>(ap, Wo, out, T_SEQ, C_DIM, C_DIM);
}

// round 2
// speedup vs baseline: 1.5284x; 1.5284x over previous
#include <cuda_runtime.h>

#define T_SEQ 4096
#define C_DIM 1024
#define NH    16
#define DHEAD 64
#define BANDW 128

// Scratch (allocation-free rule: __device__ globals)
__device__ float g_q[T_SEQ * C_DIM];
__device__ float g_k[T_SEQ * C_DIM];
__device__ float g_v[T_SEQ * C_DIM];
__device__ float g_att[T_SEQ * C_DIM];

// ----------------------------------------------------------------------------
// C[M,N] = A[M,K] @ B[N,K]^T   (row-major; M,N multiples of 128, K multiple of 8)
// 128x128 block tile, BK=8, 256 threads, 8x8 microtile.
// ----------------------------------------------------------------------------
__global__ __launch_bounds__(256) void sgemm_abt(const float* __restrict__ A,
                                                 const float* __restrict__ B,
                                                 float* __restrict__ C,
                                                 int M, int N, int K) {
    __shared__ float As[8][128];
    __shared__ float Bs[8][128];

    const int tid = threadIdx.x;
    const int m0 = blockIdx.y * 128;
    const int n0 = blockIdx.x * 128;
    const int tx = tid & 15;        // 0..15
    const int ty = tid >> 4;        // 0..15
    const int lr = tid >> 1;        // 0..127 (tile row for loads)
    const int lc = (tid & 1) * 4;   // 0 or 4

    float acc[8][8];
#pragma unroll
    for (int i = 0; i < 8; i++)
#pragma unroll
        for (int j = 0; j < 8; j++) acc[i][j] = 0.0f;

    const float* Ap = A + (size_t)(m0 + lr) * K + lc;
    const float* Bp = B + (size_t)(n0 + lr) * K + lc;

    for (int k0 = 0; k0 < K; k0 += 8) {
        float4 a = *(const float4*)(Ap + k0);
        float4 b = *(const float4*)(Bp + k0);
        As[lc + 0][lr] = a.x; As[lc + 1][lr] = a.y;
        As[lc + 2][lr] = a.z; As[lc + 3][lr] = a.w;
        Bs[lc + 0][lr] = b.x; Bs[lc + 1][lr] = b.y;
        Bs[lc + 2][lr] = b.z; Bs[lc + 3][lr] = b.w;
        __syncthreads();

#pragma unroll
        for (int kk = 0; kk < 8; kk++) {
            float4 a0 = *(const float4*)&As[kk][ty * 8];
            float4 a1 = *(const float4*)&As[kk][ty * 8 + 4];
            float4 b0 = *(const float4*)&Bs[kk][tx * 8];
            float4 b1 = *(const float4*)&Bs[kk][tx * 8 + 4];
            float ar[8] = {a0.x, a0.y, a0.z, a0.w, a1.x, a1.y, a1.z, a1.w};
            float br[8] = {b0.x, b0.y, b0.z, b0.w, b1.x, b1.y, b1.z, b1.w};
#pragma unroll
            for (int i = 0; i < 8; i++)
#pragma unroll
                for (int j = 0; j < 8; j++)
                    acc[i][j] = fmaf(ar[i], br[j], acc[i][j]);
        }
        __syncthreads();
    }

#pragma unroll
    for (int i = 0; i < 8; i++) {
        int m = m0 + ty * 8 + i;
        float* Crow = C + (size_t)m * N + n0 + tx * 8;
#pragma unroll
        for (int j = 0; j < 8; j += 4) {
            float4 o = make_float4(acc[i][j], acc[i][j + 1], acc[i][j + 2], acc[i][j + 3]);
            *(float4*)(Crow + j) = o;
        }
    }
}

// ----------------------------------------------------------------------------
// Banded causal attention, GEMM-style register tiling.
//
// Block = (64-query tile, head), 256 threads, 208KB dynamic smem, 1 CTA/SM.
// Keys staged: j in [0,192) -> global jg = t0 - 128 + j.
//
// Phase A: S = Q@K^T, 8x8 microtiles, 192 threads (8 qr x 24 kc), operands
//          transposed+XOR-swizzled in smem -> 4 LDS.128 per 64 FMA.
// Softmax: 4 lanes per query row (shfl reduce), writes P transposed+swizzled.
// Phase B: O = P@V, 8x8 microtiles, j split 4-ways (256 = 8x8x4 threads),
//          partials reduced through smem, coalesced float4 gmem store.
// ----------------------------------------------------------------------------
#define QT 64
#define KT 192
// floats: Qs 4096 | Ks 12288 | Vs 12288 | S 12288 | Pt 12288 = 53248 floats
#define ATTN_SMEM (53248 * sizeof(float))   // 212992 B

__global__ __launch_bounds__(256, 1) void attn_kernel(const float* __restrict__ q,
                                                      const float* __restrict__ k,
                                                      const float* __restrict__ v,
                                                      float* __restrict__ y) {
    extern __shared__ float sh[];
    float* Qs = sh;            // [64][64]  transposed: (d, i') swizzled
    float* Ks = sh + 4096;     // [64][192] transposed: (d, j') swizzled
    float* Vs = sh + 16384;    // [192][64] row-major (j, c)
    float* S  = sh + 28672;    // [64][192] row-major (qi, j); reused for partials
    float* Pt = sh + 40960;    // [192][64] transposed: (j, qi') swizzled

    const int h   = blockIdx.y;
    const int t0  = blockIdx.x * QT;
    const int tid = threadIdx.x;
    const int hoff = h * DHEAD;

    // ---- load Q (transpose + swizzle) ----
    for (int idx = tid; idx < QT * 16; idx += 256) {
        int i  = idx >> 4;
        int c4 = (idx & 15) * 4;
        float4 qv = *(const float4*)&q[(size_t)(t0 + i) * C_DIM + hoff + c4];
        int col = i ^ (((c4 >> 2) & 7) << 3);
        Qs[(c4 + 0) * 64 + col] = qv.x;
        Qs[(c4 + 1) * 64 + col] = qv.y;
        Qs[(c4 + 2) * 64 + col] = qv.z;
        Qs[(c4 + 3) * 64 + col] = qv.w;
    }
    // ---- load K (transpose + swizzle) and V (row-major) ----
    for (int idx = tid; idx < KT * 16; idx += 256) {
        int j  = idx >> 4;
        int c4 = (idx & 15) * 4;
        int jg = t0 - BANDW + j;
        float4 kv = make_float4(0.f, 0.f, 0.f, 0.f);
        float4 vv = make_float4(0.f, 0.f, 0.f, 0.f);
        if (jg >= 0) {
            kv = *(const float4*)&k[(size_t)jg * C_DIM + hoff + c4];
            vv = *(const float4*)&v[(size_t)jg * C_DIM + hoff + c4];
        }
        int col = j ^ (((c4 >> 2) & 7) << 3);
        Ks[(c4 + 0) * KT + col] = kv.x;
        Ks[(c4 + 1) * KT + col] = kv.y;
        Ks[(c4 + 2) * KT + col] = kv.z;
        Ks[(c4 + 3) * KT + col] = kv.w;
        *(float4*)&Vs[j * 64 + c4] = vv;
    }
    __syncthreads();

    // ---- Phase A: S = Q@K^T (192 threads, 8x8 tiles) ----
    if (tid < 192) {
        const int qr = tid / 24;
        const int kc = tid % 24;
        const int qb = qr * 8;
        const int kb = kc * 8;
        float acc[8][8];
#pragma unroll
        for (int i = 0; i < 8; i++)
#pragma unroll
            for (int j = 0; j < 8; j++) acc[i][j] = 0.0f;

#pragma unroll 8
        for (int d = 0; d < 64; d++) {
            int g = ((d >> 2) & 7) << 3;
            const float4* Qp = (const float4*)(Qs + d * 64 + (qb ^ g));
            const float4* Kp = (const float4*)(Ks + d * KT + (kb ^ g));
            float4 q0 = Qp[0], q1 = Qp[1];
            float4 k0 = Kp[0], k1 = Kp[1];
            float qv[8] = {q0.x, q0.y, q0.z, q0.w, q1.x, q1.y, q1.z, q1.w};
            float kv[8] = {k0.x, k0.y, k0.z, k0.w, k1.x, k1.y, k1.z, k1.w};
#pragma unroll
            for (int i = 0; i < 8; i++)
#pragma unroll
                for (int j = 0; j < 8; j++)
                    acc[i][j] = fmaf(qv[i], kv[j], acc[i][j]);
        }
#pragma unroll
        for (int r = 0; r < 8; r++) {
            float* Sr = S + (qb + r) * KT + kb;
            *(float4*)(Sr)     = make_float4(acc[r][0], acc[r][1], acc[r][2], acc[r][3]);
            *(float4*)(Sr + 4) = make_float4(acc[r][4], acc[r][5], acc[r][6], acc[r][7]);
        }
    }
    __syncthreads();

    // ---- Softmax (4 lanes per query row) ----
    {
        const int qi  = tid >> 2;
        const int sub = tid & 3;
        const int i   = t0 + qi;
        float s[48];
        float mx = -1e30f;
#pragma unroll
        for (int n = 0; n < 48; n++) {
            int j  = sub + 4 * n;
            int jg = t0 - BANDW + j;
            float d = S[qi * KT + j];
            bool valid = (jg >= 0) && (jg <= i) && ((i - jg) < BANDW);
            s[n] = valid ? d * 0.125f : -1e30f;   // 1/sqrt(64)
            mx = fmaxf(mx, s[n]);
        }
        mx = fmaxf(mx, __shfl_xor_sync(0xFFFFFFFFu, mx, 1));
        mx = fmaxf(mx, __shfl_xor_sync(0xFFFFFFFFu, mx, 2));

        float sum = 0.0f;
#pragma unroll
        for (int n = 0; n < 48; n++) {
            s[n] = __expf(s[n] - mx);
            sum += s[n];
        }
        sum += __shfl_xor_sync(0xFFFFFFFFu, sum, 1);
        sum += __shfl_xor_sync(0xFFFFFFFFu, sum, 2);
        float inv = 1.0f / sum;

#pragma unroll
        for (int n = 0; n < 48; n++) {
            int j = sub + 4 * n;
            int col = qi ^ (((j >> 2) & 7) << 3);
            Pt[j * 64 + col] = s[n] * inv;
        }
    }
    __syncthreads();

    // ---- Phase B: O = P@V (256 threads = 8 qr x 8 cc x 4 jgrp) ----
    {
        const int jgrp = tid >> 6;
        const int t    = tid & 63;
        const int qr   = t >> 3;
        const int cc   = t & 7;
        const int qb   = qr * 8;
        const int cb   = cc * 8;
        float acc[8][8];
#pragma unroll
        for (int i = 0; i < 8; i++)
#pragma unroll
            for (int j = 0; j < 8; j++) acc[i][j] = 0.0f;

#pragma unroll 8
        for (int n = 0; n < 48; n++) {
            int j = jgrp * 48 + n;
            int g = ((j >> 2) & 7) << 3;
            const float4* Pp = (const float4*)(Pt + j * 64 + (qb ^ g));
            const float4* Vp = (const float4*)(Vs + j * 64 + cb);
            float4 p0 = Pp[0], p1 = Pp[1];
            float4 v0 = Vp[0], v1 = Vp[1];
            float pv[8] = {p0.x, p0.y, p0.z, p0.w, p1.x, p1.y, p1.z, p1.w};
            float vv[8] = {v0.x, v0.y, v0.z, v0.w, v1.x, v1.y, v1.z, v1.w};
#pragma unroll
            for (int r = 0; r < 8; r++)
#pragma unroll
                for (int c = 0; c < 8; c++)
                    acc[r][c] = fmaf(pv[r], vv[c], acc[r][c]);
        }

        // store partials: jgrp 0 -> Qs (16KB, free), jgrp 1..3 -> S region
        float* part = (jgrp == 0) ? Qs : (S + (jgrp - 1) * 4096);
#pragma unroll
        for (int r = 0; r < 8; r++) {
            float* pr = part + (qb + r) * 64 + cb;
            *(float4*)(pr)     = make_float4(acc[r][0], acc[r][1], acc[r][2], acc[r][3]);
            *(float4*)(pr + 4) = make_float4(acc[r][4], acc[r][5], acc[r][6], acc[r][7]);
        }
    }
    __syncthreads();

    // ---- reduce 4 partials, coalesced write ----
    for (int idx = tid; idx < QT * 16; idx += 256) {
        int row = idx >> 4;
        int c4  = (idx & 15) * 4;
        int off = row * 64 + c4;
        float4 a = *(float4*)(Qs + off);
        float4 b = *(float4*)(S + off);
        float4 c = *(float4*)(S + 4096 + off);
        float4 d = *(float4*)(S + 8192 + off);
        float4 o = make_float4(a.x + b.x + c.x + d.x,
                               a.y + b.y + c.y + d.y,
                               a.z + b.z + c.z + d.z,
                               a.w + b.w + c.w + d.w);
        *(float4*)&y[(size_t)(t0 + row) * C_DIM + hoff + c4] = o;
    }
}

// ----------------------------------------------------------------------------
extern "C" void kernel_launch(void* const* d_in, const int* in_sizes, int n_in,
                              void* d_out, int out_size) {
    const float* x  = (const float*)d_in[0];
    const float* Wq = (const float*)d_in[1];
    const float* Wk = (const float*)d_in[2];
    const float* Wv = (const float*)d_in[3];
    const float* Wo = (const float*)d_in[4];
    float* out = (float*)d_out;

    float *qp, *kp, *vp, *ap;
    cudaGetSymbolAddress((void**)&qp, g_q);
    cudaGetSymbolAddress((void**)&kp, g_k);
    cudaGetSymbolAddress((void**)&vp, g_v);
    cudaGetSymbolAddress((void**)&ap, g_att);

    cudaFuncSetAttribute(attn_kernel, cudaFuncAttributeMaxDynamicSharedMemorySize,
                         (int)ATTN_SMEM);

    dim3 gg(C_DIM / 128, T_SEQ / 128);
    sgemm_abt<<<gg, 256>>>(x, Wq, qp, T_SEQ, C_DIM, C_DIM);
    sgemm_abt<<<gg, 256>>>(x, Wk, kp, T_SEQ, C_DIM, C_DIM);
    sgemm_abt<<<gg, 256>>>(x, Wv, vp, T_SEQ, C_DIM, C_DIM);

    attn_kernel<<<dim3(T_SEQ / QT, NH), 256, ATTN_SMEM>>>(qp, kp, vp, ap);

    sgemm_abt<<<gg, 256>>>(ap, Wo, out, T_SEQ, C_DIM, C_DIM);
}

// round 4
// speedup vs baseline: 3.1480x; 2.0596x over previous
#include <cuda_runtime.h>
#include <cuda_bf16.h>
#include <cstdint>

#define T_SEQ 4096
#define C_DIM 1024
#define NH    16
#define DHEAD 64
#define BANDW 128

// ---------------------------------------------------------------------------
// Scratch (__device__ globals; allocation-free rule)
// ---------------------------------------------------------------------------
__device__ float g_q[T_SEQ * C_DIM];
__device__ float g_k[T_SEQ * C_DIM];
__device__ float g_v[T_SEQ * C_DIM];
__device__ float g_att[T_SEQ * C_DIM];

__device__ __nv_bfloat16 g_xhi[T_SEQ * C_DIM];
__device__ __nv_bfloat16 g_xlo[T_SEQ * C_DIM];
__device__ __nv_bfloat16 g_ahi[T_SEQ * C_DIM];
__device__ __nv_bfloat16 g_alo[T_SEQ * C_DIM];
__device__ __nv_bfloat16 g_whi[4][C_DIM * C_DIM];
__device__ __nv_bfloat16 g_wlo[4][C_DIM * C_DIM];

// ---------------------------------------------------------------------------
// PTX helpers (base features only — must compile on compute_103 PTX target)
// ---------------------------------------------------------------------------
__device__ __forceinline__ uint32_t smem_u32(const void* p) {
    uint32_t a;
    asm("{ .reg .u64 t; cvta.to.shared.u64 t, %1; cvt.u32.u64 %0, t; }" : "=r"(a) : "l"(p));
    return a;
}
__device__ __forceinline__ void cp16(uint32_t dst, const void* src) {
    asm volatile("cp.async.cg.shared.global [%0], [%1], 16;" :: "r"(dst), "l"(src));
}
__device__ __forceinline__ void cp_commit() {
    asm volatile("cp.async.commit_group;" ::: "memory");
}
__device__ __forceinline__ void ldm_x4(uint32_t* r, uint32_t a) {
    asm volatile("ldmatrix.sync.aligned.m8n8.x4.shared.b16 {%0,%1,%2,%3}, [%4];"
                 : "=r"(r[0]), "=r"(r[1]), "=r"(r[2]), "=r"(r[3]) : "r"(a));
}
__device__ __forceinline__ void mma16816(float* d, const uint32_t* a, const uint32_t* b) {
    asm volatile("mma.sync.aligned.m16n8k16.row.col.f32.bf16.bf16.f32 "
                 "{%0,%1,%2,%3}, {%4,%5,%6,%7}, {%8,%9}, {%0,%1,%2,%3};"
                 : "+f"(d[0]), "+f"(d[1]), "+f"(d[2]), "+f"(d[3])
                 : "r"(a[0]), "r"(a[1]), "r"(a[2]), "r"(a[3]), "r"(b[0]), "r"(b[1]));
}

// ---------------------------------------------------------------------------
// fp32 -> (hi, lo) bf16 split
// ---------------------------------------------------------------------------
__global__ __launch_bounds__(256) void split_kernel(const float* __restrict__ in,
                                                    __nv_bfloat16* __restrict__ hi,
                                                    __nv_bfloat16* __restrict__ lo,
                                                    int n4) {
    int i = blockIdx.x * 256 + threadIdx.x;
    if (i >= n4) return;
    float4 v = ((const float4*)in)[i];
    __nv_bfloat16 h0 = __float2bfloat16(v.x), h1 = __float2bfloat16(v.y);
    __nv_bfloat16 h2 = __float2bfloat16(v.z), h3 = __float2bfloat16(v.w);
    __nv_bfloat16 l0 = __float2bfloat16(v.x - __bfloat162float(h0));
    __nv_bfloat16 l1 = __float2bfloat16(v.y - __bfloat162float(h1));
    __nv_bfloat16 l2 = __float2bfloat16(v.z - __bfloat162float(h2));
    __nv_bfloat16 l3 = __float2bfloat16(v.w - __bfloat162float(h3));
    __nv_bfloat162* hp = (__nv_bfloat162*)(hi + 4 * (size_t)i);
    __nv_bfloat162* lp = (__nv_bfloat162*)(lo + 4 * (size_t)i);
    hp[0] = __nv_bfloat162(h0, h1); hp[1] = __nv_bfloat162(h2, h3);
    lp[0] = __nv_bfloat162(l0, l1); lp[1] = __nv_bfloat162(l2, l3);
}

// ---------------------------------------------------------------------------
// Tensor-core GEMM via mma.sync (bf16, fp32 accum):
//   C[M,N] = Ahi@Bhi^T + Ahi@Blo^T + Alo@Bhi^T    (A:[M,K], B:[N,K] bf16)
// CTA tile 128x128, BK=32, 256 threads = 2x4 warps (warp tile 64x32),
// 3-stage cp.async pipeline. Each stage holds 4 tiles (Ahi,Alo,Bhi,Blo),
// 80B-padded rows for conflict-free ldmatrix.
// ---------------------------------------------------------------------------
#define BM 128
#define BN 128
#define BK 32
#define GK C_DIM
#define NCHUNK (GK / BK)          // 32
#define ROWB 80                   // 32 bf16 = 64B, padded to 80B
#define TILEB (128 * ROWB)        // 10240 B per tile
#define STAGEB (4 * TILEB)        // 40960 B per stage
#define GEMM_SMEM (3 * STAGEB)    // 122880 B

__global__ __launch_bounds__(256) void mma_gemm(const __nv_bfloat16* __restrict__ Ahi,
                                                const __nv_bfloat16* __restrict__ Alo,
                                                const __nv_bfloat16* __restrict__ Bhi,
                                                const __nv_bfloat16* __restrict__ Blo,
                                                float* __restrict__ C, int M, int N) {
    extern __shared__ __align__(128) char smem[];
    const uint32_t sbase = smem_u32(smem);
    const int tid  = threadIdx.x;
    const int lane = tid & 31;
    const int warp = tid >> 5;
    const int warp_m = warp >> 2;       // 0..1
    const int warp_n = warp & 3;        // 0..3
    const int m0 = blockIdx.y * BM;
    const int n0 = blockIdx.x * BN;

    // ---- load mapping: each thread does 2 rows per tile (rows r0, r0+64) ----
    const int r0 = tid >> 2;            // 0..63
    const int q  = tid & 3;             // 16B quarter of 64B row
    const __nv_bfloat16* tb[4] = {
        Ahi + (size_t)m0 * GK, Alo + (size_t)m0 * GK,
        Bhi + (size_t)n0 * GK, Blo + (size_t)n0 * GK };

#define LOAD_STAGE(s, c)                                                        \
    {                                                                           \
        const int k0_ = (c) * BK;                                               \
        const uint32_t ds_ = sbase + (s) * STAGEB;                              \
        _Pragma("unroll")                                                       \
        for (int t_ = 0; t_ < 4; t_++) {                                        \
            _Pragma("unroll")                                                   \
            for (int h_ = 0; h_ < 2; h_++) {                                    \
                int row_ = r0 + h_ * 64;                                        \
                cp16(ds_ + t_ * TILEB + row_ * ROWB + q * 16,                   \
                     tb[t_] + (size_t)row_ * GK + k0_ + q * 8);                 \
            }                                                                   \
        }                                                                       \
        cp_commit();                                                            \
    }

    // ---- ldmatrix per-lane address offsets ----
    const int sel = lane >> 3;          // matrix select 0..3
    const int l7  = lane & 7;
    // A: m0/m1 rows +0/+8 (k0-7), m2/m3 rows +0/+8 (k8-15)
    const uint32_t aoff = (uint32_t)((warp_m * 64 + (sel & 1) * 8 + l7) * ROWB + (sel >> 1) * 16);
    // B: m0/m1 = n-tile even k0-7/k8-15, m2/m3 = n-tile odd
    const uint32_t boff = (uint32_t)((warp_n * 32 + (sel >> 1) * 8 + l7) * ROWB + (sel & 1) * 16);

    float acc[4][4][4];
#pragma unroll
    for (int i = 0; i < 4; i++)
#pragma unroll
        for (int j = 0; j < 4; j++)
#pragma unroll
            for (int e = 0; e < 4; e++) acc[i][j][e] = 0.0f;

    // ---- prologue: stages for chunks 0,1 ----
    LOAD_STAGE(0, 0);
    LOAD_STAGE(1, 1);

    for (int c = 0; c < NCHUNK; c++) {
        if (c == NCHUNK - 1) asm volatile("cp.async.wait_group 0;" ::: "memory");
        else                 asm volatile("cp.async.wait_group 1;" ::: "memory");
        __syncthreads();

        if (c + 2 < NCHUNK) LOAD_STAGE((c + 2) % 3, c + 2);

        const uint32_t ds = sbase + (c % 3) * STAGEB;
        const uint32_t sAh = ds + 0 * TILEB + aoff;
        const uint32_t sAl = ds + 1 * TILEB + aoff;
        const uint32_t sBh = ds + 2 * TILEB + boff;
        const uint32_t sBl = ds + 3 * TILEB + boff;

#pragma unroll
        for (int ks = 0; ks < 2; ks++) {
            const uint32_t ka = ks * 32;   // 16 bf16 = 32 bytes per k-step
            uint32_t Ah[4][4], Al[4][4], Bh[4][2], Bl[4][2];
#pragma unroll
            for (int mt = 0; mt < 4; mt++) {
                ldm_x4(Ah[mt], sAh + mt * (16 * ROWB) + ka);
                ldm_x4(Al[mt], sAl + mt * (16 * ROWB) + ka);
            }
#pragma unroll
            for (int p = 0; p < 2; p++) {
                uint32_t rh[4], rl[4];
                ldm_x4(rh, sBh + p * (16 * ROWB) + ka);
                ldm_x4(rl, sBl + p * (16 * ROWB) + ka);
                Bh[2 * p][0] = rh[0]; Bh[2 * p][1] = rh[1];
                Bh[2 * p + 1][0] = rh[2]; Bh[2 * p + 1][1] = rh[3];
                Bl[2 * p][0] = rl[0]; Bl[2 * p][1] = rl[1];
                Bl[2 * p + 1][0] = rl[2]; Bl[2 * p + 1][1] = rl[3];
            }
            // three passes: hi*hi, hi*lo, lo*hi (16 independent mma per pass)
#pragma unroll
            for (int mt = 0; mt < 4; mt++)
#pragma unroll
                for (int nt = 0; nt < 4; nt++)
                    mma16816(acc[mt][nt], Ah[mt], Bh[nt]);
#pragma unroll
            for (int mt = 0; mt < 4; mt++)
#pragma unroll
                for (int nt = 0; nt < 4; nt++)
                    mma16816(acc[mt][nt], Ah[mt], Bl[nt]);
#pragma unroll
            for (int mt = 0; mt < 4; mt++)
#pragma unroll
                for (int nt = 0; nt < 4; nt++)
                    mma16816(acc[mt][nt], Al[mt], Bh[nt]);
        }
        __syncthreads();
    }

    // ---- epilogue: fp32 stores, 8B (2 cols) per thread per row-tile ----
    const int er = lane >> 2;           // 0..7
    const int ec = (lane & 3) * 2;
#pragma unroll
    for (int mt = 0; mt < 4; mt++) {
        const int row = m0 + warp_m * 64 + mt * 16 + er;
#pragma unroll
        for (int nt = 0; nt < 4; nt++) {
            const int col = n0 + warp_n * 32 + nt * 8 + ec;
            *(float2*)&C[(size_t)row * N + col] =
                make_float2(acc[mt][nt][0], acc[mt][nt][1]);
            *(float2*)&C[(size_t)(row + 8) * N + col] =
                make_float2(acc[mt][nt][2], acc[mt][nt][3]);
        }
    }
#undef LOAD_STAGE
}

// ---------------------------------------------------------------------------
// Banded causal attention (round-2 version: 156us)
// ---------------------------------------------------------------------------
#define QT 64
#define KT 192
#define ATTN_SMEM (53248 * sizeof(float))

__global__ __launch_bounds__(256, 1) void attn_kernel(const float* __restrict__ q,
                                                      const float* __restrict__ k,
                                                      const float* __restrict__ v,
                                                      float* __restrict__ y) {
    extern __shared__ float sh[];
    float* Qs = sh;
    float* Ks = sh + 4096;
    float* Vs = sh + 16384;
    float* S  = sh + 28672;
    float* Pt = sh + 40960;

    const int h   = blockIdx.y;
    const int t0  = blockIdx.x * QT;
    const int tid = threadIdx.x;
    const int hoff = h * DHEAD;

    for (int idx = tid; idx < QT * 16; idx += 256) {
        int i  = idx >> 4;
        int c4 = (idx & 15) * 4;
        float4 qv = *(const float4*)&q[(size_t)(t0 + i) * C_DIM + hoff + c4];
        int col = i ^ (((c4 >> 2) & 7) << 3);
        Qs[(c4 + 0) * 64 + col] = qv.x;
        Qs[(c4 + 1) * 64 + col] = qv.y;
        Qs[(c4 + 2) * 64 + col] = qv.z;
        Qs[(c4 + 3) * 64 + col] = qv.w;
    }
    for (int idx = tid; idx < KT * 16; idx += 256) {
        int j  = idx >> 4;
        int c4 = (idx & 15) * 4;
        int jg = t0 - BANDW + j;
        float4 kv = make_float4(0.f, 0.f, 0.f, 0.f);
        float4 vv = make_float4(0.f, 0.f, 0.f, 0.f);
        if (jg >= 0) {
            kv = *(const float4*)&k[(size_t)jg * C_DIM + hoff + c4];
            vv = *(const float4*)&v[(size_t)jg * C_DIM + hoff + c4];
        }
        int col = j ^ (((c4 >> 2) & 7) << 3);
        Ks[(c4 + 0) * KT + col] = kv.x;
        Ks[(c4 + 1) * KT + col] = kv.y;
        Ks[(c4 + 2) * KT + col] = kv.z;
        Ks[(c4 + 3) * KT + col] = kv.w;
        *(float4*)&Vs[j * 64 + c4] = vv;
    }
    __syncthreads();

    if (tid < 192) {
        const int qr = tid / 24;
        const int kc = tid % 24;
        const int qb = qr * 8;
        const int kb = kc * 8;
        float acc[8][8];
#pragma unroll
        for (int i = 0; i < 8; i++)
#pragma unroll
            for (int j = 0; j < 8; j++) acc[i][j] = 0.0f;

#pragma unroll 8
        for (int d = 0; d < 64; d++) {
            int g = ((d >> 2) & 7) << 3;
            const float4* Qp = (const float4*)(Qs + d * 64 + (qb ^ g));
            const float4* Kp = (const float4*)(Ks + d * KT + (kb ^ g));
            float4 q0 = Qp[0], q1 = Qp[1];
            float4 k0 = Kp[0], k1 = Kp[1];
            float qv[8] = {q0.x, q0.y, q0.z, q0.w, q1.x, q1.y, q1.z, q1.w};
            float kv[8] = {k0.x, k0.y, k0.z, k0.w, k1.x, k1.y, k1.z, k1.w};
#pragma unroll
            for (int i = 0; i < 8; i++)
#pragma unroll
                for (int j = 0; j < 8; j++)
                    acc[i][j] = fmaf(qv[i], kv[j], acc[i][j]);
        }
#pragma unroll
        for (int r = 0; r < 8; r++) {
            float* Sr = S + (qb + r) * KT + kb;
            *(float4*)(Sr)     = make_float4(acc[r][0], acc[r][1], acc[r][2], acc[r][3]);
            *(float4*)(Sr + 4) = make_float4(acc[r][4], acc[r][5], acc[r][6], acc[r][7]);
        }
    }
    __syncthreads();

    {
        const int qi  = tid >> 2;
        const int sub = tid & 3;
        const int i   = t0 + qi;
        float s[48];
        float mx = -1e30f;
#pragma unroll
        for (int n = 0; n < 48; n++) {
            int j  = sub + 4 * n;
            int jg = t0 - BANDW + j;
            float d = S[qi * KT + j];
            bool valid = (jg >= 0) && (jg <= i) && ((i - jg) < BANDW);
            s[n] = valid ? d * 0.125f : -1e30f;
            mx = fmaxf(mx, s[n]);
        }
        mx = fmaxf(mx, __shfl_xor_sync(0xFFFFFFFFu, mx, 1));
        mx = fmaxf(mx, __shfl_xor_sync(0xFFFFFFFFu, mx, 2));

        float sum = 0.0f;
#pragma unroll
        for (int n = 0; n < 48; n++) {
            s[n] = __expf(s[n] - mx);
            sum += s[n];
        }
        sum += __shfl_xor_sync(0xFFFFFFFFu, sum, 1);
        sum += __shfl_xor_sync(0xFFFFFFFFu, sum, 2);
        float inv = 1.0f / sum;

#pragma unroll
        for (int n = 0; n < 48; n++) {
            int j = sub + 4 * n;
            int col = qi ^ (((j >> 2) & 7) << 3);
            Pt[j * 64 + col] = s[n] * inv;
        }
    }
    __syncthreads();

    {
        const int jgrp = tid >> 6;
        const int t    = tid & 63;
        const int qr   = t >> 3;
        const int cc   = t & 7;
        const int qb   = qr * 8;
        const int cb   = cc * 8;
        float acc[8][8];
#pragma unroll
        for (int i = 0; i < 8; i++)
#pragma unroll
            for (int j = 0; j < 8; j++) acc[i][j] = 0.0f;

#pragma unroll 8
        for (int n = 0; n < 48; n++) {
            int j = jgrp * 48 + n;
            int g = ((j >> 2) & 7) << 3;
            const float4* Pp = (const float4*)(Pt + j * 64 + (qb ^ g));
            const float4* Vp = (const float4*)(Vs + j * 64 + cb);
            float4 p0 = Pp[0], p1 = Pp[1];
            float4 v0 = Vp[0], v1 = Vp[1];
            float pv[8] = {p0.x, p0.y, p0.z, p0.w, p1.x, p1.y, p1.z, p1.w};
            float vv[8] = {v0.x, v0.y, v0.z, v0.w, v1.x, v1.y, v1.z, v1.w};
#pragma unroll
            for (int r = 0; r < 8; r++)
#pragma unroll
                for (int c = 0; c < 8; c++)
                    acc[r][c] = fmaf(pv[r], vv[c], acc[r][c]);
        }

        float* part = (jgrp == 0) ? Qs : (S + (jgrp - 1) * 4096);
#pragma unroll
        for (int r = 0; r < 8; r++) {
            float* pr = part + (qb + r) * 64 + cb;
            *(float4*)(pr)     = make_float4(acc[r][0], acc[r][1], acc[r][2], acc[r][3]);
            *(float4*)(pr + 4) = make_float4(acc[r][4], acc[r][5], acc[r][6], acc[r][7]);
        }
    }
    __syncthreads();

    for (int idx = tid; idx < QT * 16; idx += 256) {
        int row = idx >> 4;
        int c4  = (idx & 15) * 4;
        int off = row * 64 + c4;
        float4 a = *(float4*)(Qs + off);
        float4 b = *(float4*)(S + off);
        float4 c = *(float4*)(S + 4096 + off);
        float4 d = *(float4*)(S + 8192 + off);
        float4 o = make_float4(a.x + b.x + c.x + d.x,
                               a.y + b.y + c.y + d.y,
                               a.z + b.z + c.z + d.z,
                               a.w + b.w + c.w + d.w);
        *(float4*)&y[(size_t)(t0 + row) * C_DIM + hoff + c4] = o;
    }
}

// ---------------------------------------------------------------------------
extern "C" void kernel_launch(void* const* d_in, const int* in_sizes, int n_in,
                              void* d_out, int out_size) {
    const float* x  = (const float*)d_in[0];
    const float* Wq = (const float*)d_in[1];
    const float* Wk = (const float*)d_in[2];
    const float* Wv = (const float*)d_in[3];
    const float* Wo = (const float*)d_in[4];
    float* out = (float*)d_out;

    float *qp, *kp, *vp, *ap;
    __nv_bfloat16 *xhi, *xlo, *ahi, *alo, *whi, *wlo;
    cudaGetSymbolAddress((void**)&qp, g_q);
    cudaGetSymbolAddress((void**)&kp, g_k);
    cudaGetSymbolAddress((void**)&vp, g_v);
    cudaGetSymbolAddress((void**)&ap, g_att);
    cudaGetSymbolAddress((void**)&xhi, g_xhi);
    cudaGetSymbolAddress((void**)&xlo, g_xlo);
    cudaGetSymbolAddress((void**)&ahi, g_ahi);
    cudaGetSymbolAddress((void**)&alo, g_alo);
    cudaGetSymbolAddress((void**)&whi, g_whi);
    cudaGetSymbolAddress((void**)&wlo, g_wlo);

    cudaFuncSetAttribute(attn_kernel, cudaFuncAttributeMaxDynamicSharedMemorySize,
                         (int)ATTN_SMEM);
    cudaFuncSetAttribute(mma_gemm, cudaFuncAttributeMaxDynamicSharedMemorySize,
                         GEMM_SMEM);

    const int NX4 = T_SEQ * C_DIM / 4;
    const int NW4 = C_DIM * C_DIM / 4;
    const size_t WSZ = (size_t)C_DIM * C_DIM;

    split_kernel<<<(NX4 + 255) / 256, 256>>>(x, xhi, xlo, NX4);
    split_kernel<<<(NW4 + 255) / 256, 256>>>(Wq, whi + 0 * WSZ, wlo + 0 * WSZ, NW4);
    split_kernel<<<(NW4 + 255) / 256, 256>>>(Wk, whi + 1 * WSZ, wlo + 1 * WSZ, NW4);
    split_kernel<<<(NW4 + 255) / 256, 256>>>(Wv, whi + 2 * WSZ, wlo + 2 * WSZ, NW4);
    split_kernel<<<(NW4 + 255) / 256, 256>>>(Wo, whi + 3 * WSZ, wlo + 3 * WSZ, NW4);

    dim3 gg(C_DIM / BN, T_SEQ / BM);
    mma_gemm<<<gg, 256, GEMM_SMEM>>>(xhi, xlo, whi + 0 * WSZ, wlo + 0 * WSZ, qp, T_SEQ, C_DIM);
    mma_gemm<<<gg, 256, GEMM_SMEM>>>(xhi, xlo, whi + 1 * WSZ, wlo + 1 * WSZ, kp, T_SEQ, C_DIM);
    mma_gemm<<<gg, 256, GEMM_SMEM>>>(xhi, xlo, whi + 2 * WSZ, wlo + 2 * WSZ, vp, T_SEQ, C_DIM);

    attn_kernel<<<dim3(T_SEQ / QT, NH), 256, ATTN_SMEM>>>(qp, kp, vp, ap);

    split_kernel<<<(NX4 + 255) / 256, 256>>>(ap, ahi, alo, NX4);
    mma_gemm<<<gg, 256, GEMM_SMEM>>>(ahi, alo, whi + 3 * WSZ, wlo + 3 * WSZ, out, T_SEQ, C_DIM);
}

// round 5
// speedup vs baseline: 3.8552x; 1.2247x over previous
#include <cuda_runtime.h>
#include <cuda_bf16.h>
#include <cstdint>

#define T_SEQ 4096
#define C_DIM 1024
#define NH    16
#define DHEAD 64
#define BANDW 128

typedef __nv_bfloat16  bf16;
typedef __nv_bfloat162 bf162;

// ---------------------------------------------------------------------------
// Scratch (__device__ globals; allocation-free rule)
// ---------------------------------------------------------------------------
__device__ bf16 g_xhi[T_SEQ * C_DIM];
__device__ bf16 g_xlo[T_SEQ * C_DIM];
__device__ bf16 g_qhi[T_SEQ * C_DIM];
__device__ bf16 g_qlo[T_SEQ * C_DIM];
__device__ bf16 g_khi[T_SEQ * C_DIM];
__device__ bf16 g_klo[T_SEQ * C_DIM];
__device__ bf16 g_vhi[T_SEQ * C_DIM];
__device__ bf16 g_vlo[T_SEQ * C_DIM];
__device__ bf16 g_ahi[T_SEQ * C_DIM];
__device__ bf16 g_alo[T_SEQ * C_DIM];
__device__ bf16 g_whi[4][C_DIM * C_DIM];
__device__ bf16 g_wlo[4][C_DIM * C_DIM];

// ---------------------------------------------------------------------------
// PTX helpers (base features only — compute_103 PTX target)
// ---------------------------------------------------------------------------
__device__ __forceinline__ uint32_t smem_u32(const void* p) {
    uint32_t a;
    asm("{ .reg .u64 t; cvta.to.shared.u64 t, %1; cvt.u32.u64 %0, t; }" : "=r"(a) : "l"(p));
    return a;
}
__device__ __forceinline__ void cp16(uint32_t dst, const void* src) {
    asm volatile("cp.async.cg.shared.global [%0], [%1], 16;" :: "r"(dst), "l"(src));
}
__device__ __forceinline__ void cp_commit() {
    asm volatile("cp.async.commit_group;" ::: "memory");
}
__device__ __forceinline__ void stz16(uint32_t a) {
    asm volatile("st.shared.v4.u32 [%0], {%1,%1,%1,%1};" :: "r"(a), "r"(0) : "memory");
}
__device__ __forceinline__ void ldm_x4(uint32_t* r, uint32_t a) {
    asm volatile("ldmatrix.sync.aligned.m8n8.x4.shared.b16 {%0,%1,%2,%3}, [%4];"
                 : "=r"(r[0]), "=r"(r[1]), "=r"(r[2]), "=r"(r[3]) : "r"(a));
}
__device__ __forceinline__ void ldm_x4t(uint32_t* r, uint32_t a) {
    asm volatile("ldmatrix.sync.aligned.m8n8.x4.trans.shared.b16 {%0,%1,%2,%3}, [%4];"
                 : "=r"(r[0]), "=r"(r[1]), "=r"(r[2]), "=r"(r[3]) : "r"(a));
}
__device__ __forceinline__ void mma16816(float* d, const uint32_t* a, const uint32_t* b) {
    asm volatile("mma.sync.aligned.m16n8k16.row.col.f32.bf16.bf16.f32 "
                 "{%0,%1,%2,%3}, {%4,%5,%6,%7}, {%8,%9}, {%0,%1,%2,%3};"
                 : "+f"(d[0]), "+f"(d[1]), "+f"(d[2]), "+f"(d[3])
                 : "r"(a[0]), "r"(a[1]), "r"(a[2]), "r"(a[3]), "r"(b[0]), "r"(b[1]));
}
__device__ __forceinline__ void split2(float x, bf16& h, bf16& l) {
    h = __float2bfloat16(x);
    l = __float2bfloat16(x - __bfloat162float(h));
}

// ---------------------------------------------------------------------------
// fp32 -> (hi, lo) bf16 split kernels
// ---------------------------------------------------------------------------
__global__ __launch_bounds__(256) void split_kernel(const float* __restrict__ in,
                                                    bf16* __restrict__ hi,
                                                    bf16* __restrict__ lo, int n4) {
    int i = blockIdx.x * 256 + threadIdx.x;
    if (i >= n4) return;
    float4 v = ((const float4*)in)[i];
    bf16 h0, h1, h2, h3, l0, l1, l2, l3;
    split2(v.x, h0, l0); split2(v.y, h1, l1); split2(v.z, h2, l2); split2(v.w, h3, l3);
    bf162* hp = (bf162*)(hi + 4 * (size_t)i);
    bf162* lp = (bf162*)(lo + 4 * (size_t)i);
    hp[0] = bf162(h0, h1); hp[1] = bf162(h2, h3);
    lp[0] = bf162(l0, l1); lp[1] = bf162(l2, l3);
}

__global__ __launch_bounds__(256) void split_w4_kernel(const float* __restrict__ w0,
                                                       const float* __restrict__ w1,
                                                       const float* __restrict__ w2,
                                                       const float* __restrict__ w3,
                                                       bf16* __restrict__ hi,
                                                       bf16* __restrict__ lo, int n4) {
    int i = blockIdx.x * 256 + threadIdx.x;
    if (i >= n4) return;
    int wsel = blockIdx.y;
    const float* in = (wsel == 0) ? w0 : (wsel == 1) ? w1 : (wsel == 2) ? w2 : w3;
    size_t base = (size_t)wsel * (C_DIM * C_DIM);
    float4 v = ((const float4*)in)[i];
    bf16 h0, h1, h2, h3, l0, l1, l2, l3;
    split2(v.x, h0, l0); split2(v.y, h1, l1); split2(v.z, h2, l2); split2(v.w, h3, l3);
    bf162* hp = (bf162*)(hi + base + 4 * (size_t)i);
    bf162* lp = (bf162*)(lo + base + 4 * (size_t)i);
    hp[0] = bf162(h0, h1); hp[1] = bf162(h2, h3);
    lp[0] = bf162(l0, l1); lp[1] = bf162(l2, l3);
}

// ---------------------------------------------------------------------------
// Shared GEMM mainloop (bf16 hi/lo, 3-pass):  128x128 CTA tile, BK=32,
// 256 threads = 2x4 warps (warp tile 64x32), 3-stage cp.async pipeline.
// ---------------------------------------------------------------------------
#define BM 128
#define BN 128
#define BK 32
#define GK C_DIM
#define NCHUNK (GK / BK)
#define ROWB 80
#define TILEB (128 * ROWB)
#define STAGEB (4 * TILEB)
#define GEMM_SMEM (3 * STAGEB)

__device__ __forceinline__ void gemm_mainloop(uint32_t sbase, int tid,
                                              const bf16* __restrict__ tA_hi,
                                              const bf16* __restrict__ tA_lo,
                                              const bf16* __restrict__ tB_hi,
                                              const bf16* __restrict__ tB_lo,
                                              float (&acc)[4][4][4]) {
    const int lane = tid & 31;
    const int warp = tid >> 5;
    const int warp_m = warp >> 2;
    const int warp_n = warp & 3;
    const int r0 = tid >> 2;
    const int q  = tid & 3;
    const bf16* tb[4] = {tA_hi, tA_lo, tB_hi, tB_lo};

    auto load_stage = [&](int s, int c) {
        const int k0 = c * BK;
        const uint32_t ds = sbase + s * STAGEB;
#pragma unroll
        for (int t = 0; t < 4; t++) {
#pragma unroll
            for (int hh = 0; hh < 2; hh++) {
                int row = r0 + hh * 64;
                cp16(ds + t * TILEB + row * ROWB + q * 16,
                     tb[t] + (size_t)row * GK + k0 + q * 8);
            }
        }
        cp_commit();
    };

    const int sel = lane >> 3;
    const int l7  = lane & 7;
    const uint32_t aoff = (uint32_t)((warp_m * 64 + (sel & 1) * 8 + l7) * ROWB + (sel >> 1) * 16);
    const uint32_t boff = (uint32_t)((warp_n * 32 + (sel >> 1) * 8 + l7) * ROWB + (sel & 1) * 16);

    load_stage(0, 0);
    load_stage(1, 1);

    for (int c = 0; c < NCHUNK; c++) {
        if (c == NCHUNK - 1) asm volatile("cp.async.wait_group 0;" ::: "memory");
        else                 asm volatile("cp.async.wait_group 1;" ::: "memory");
        __syncthreads();

        if (c + 2 < NCHUNK) load_stage((c + 2) % 3, c + 2);

        const uint32_t ds = sbase + (c % 3) * STAGEB;
        const uint32_t sAh = ds + 0 * TILEB + aoff;
        const uint32_t sAl = ds + 1 * TILEB + aoff;
        const uint32_t sBh = ds + 2 * TILEB + boff;
        const uint32_t sBl = ds + 3 * TILEB + boff;

#pragma unroll
        for (int ks = 0; ks < 2; ks++) {
            const uint32_t ka = ks * 32;
            uint32_t Ah[4][4], Al[4][4], Bh[4][2], Bl[4][2];
#pragma unroll
            for (int mt = 0; mt < 4; mt++) {
                ldm_x4(Ah[mt], sAh + mt * (16 * ROWB) + ka);
                ldm_x4(Al[mt], sAl + mt * (16 * ROWB) + ka);
            }
#pragma unroll
            for (int p = 0; p < 2; p++) {
                uint32_t rh[4], rl[4];
                ldm_x4(rh, sBh + p * (16 * ROWB) + ka);
                ldm_x4(rl, sBl + p * (16 * ROWB) + ka);
                Bh[2 * p][0] = rh[0]; Bh[2 * p][1] = rh[1];
                Bh[2 * p + 1][0] = rh[2]; Bh[2 * p + 1][1] = rh[3];
                Bl[2 * p][0] = rl[0]; Bl[2 * p][1] = rl[1];
                Bl[2 * p + 1][0] = rl[2]; Bl[2 * p + 1][1] = rl[3];
            }
#pragma unroll
            for (int mt = 0; mt < 4; mt++)
#pragma unroll
                for (int nt = 0; nt < 4; nt++)
                    mma16816(acc[mt][nt], Ah[mt], Bh[nt]);
#pragma unroll
            for (int mt = 0; mt < 4; mt++)
#pragma unroll
                for (int nt = 0; nt < 4; nt++)
                    mma16816(acc[mt][nt], Ah[mt], Bl[nt]);
#pragma unroll
            for (int mt = 0; mt < 4; mt++)
#pragma unroll
                for (int nt = 0; nt < 4; nt++)
                    mma16816(acc[mt][nt], Al[mt], Bh[nt]);
        }
        __syncthreads();
    }
}

// ---- Fused QKV projection: N = 3072, epilogue emits bf16 hi/lo ----
__global__ __launch_bounds__(256) void mma_gemm_qkv(const bf16* __restrict__ xhi,
                                                    const bf16* __restrict__ xlo,
                                                    const bf16* __restrict__ whi,
                                                    const bf16* __restrict__ wlo,
                                                    bf16* __restrict__ qhi, bf16* __restrict__ qlo,
                                                    bf16* __restrict__ khi, bf16* __restrict__ klo,
                                                    bf16* __restrict__ vhi, bf16* __restrict__ vlo) {
    extern __shared__ __align__(128) char smem[];
    const uint32_t sbase = smem_u32(smem);
    const int tid = threadIdx.x;
    const int which = blockIdx.x >> 3;
    const int n0 = (blockIdx.x & 7) * BN;
    const int m0 = blockIdx.y * BM;
    const size_t WSZ = (size_t)C_DIM * C_DIM;

    float acc[4][4][4];
#pragma unroll
    for (int i = 0; i < 4; i++)
#pragma unroll
        for (int j = 0; j < 4; j++)
#pragma unroll
            for (int e = 0; e < 4; e++) acc[i][j][e] = 0.0f;

    gemm_mainloop(sbase, tid,
                  xhi + (size_t)m0 * GK, xlo + (size_t)m0 * GK,
                  whi + which * WSZ + (size_t)n0 * GK,
                  wlo + which * WSZ + (size_t)n0 * GK, acc);

    bf16* oh = (which == 0) ? qhi : (which == 1) ? khi : vhi;
    bf16* ol = (which == 0) ? qlo : (which == 1) ? klo : vlo;

    const int lane = tid & 31;
    const int warp = tid >> 5;
    const int warp_m = warp >> 2;
    const int warp_n = warp & 3;
    const int er = lane >> 2;
    const int ec = (lane & 3) * 2;
#pragma unroll
    for (int mt = 0; mt < 4; mt++) {
        const int row = m0 + warp_m * 64 + mt * 16 + er;
#pragma unroll
        for (int nt = 0; nt < 4; nt++) {
            const int col = n0 + warp_n * 32 + nt * 8 + ec;
#pragma unroll
            for (int hh = 0; hh < 2; hh++) {
                float c0 = acc[mt][nt][2 * hh], c1 = acc[mt][nt][2 * hh + 1];
                bf16 h0, h1, l0, l1;
                split2(c0, h0, l0); split2(c1, h1, l1);
                size_t off = (size_t)(row + 8 * hh) * C_DIM + col;
                *(bf162*)&oh[off] = bf162(h0, h1);
                *(bf162*)&ol[off] = bf162(l0, l1);
            }
        }
    }
}

// ---- Output projection: fp32 epilogue ----
__global__ __launch_bounds__(256) void mma_gemm_f32(const bf16* __restrict__ Ahi,
                                                    const bf16* __restrict__ Alo,
                                                    const bf16* __restrict__ Bhi,
                                                    const bf16* __restrict__ Blo,
                                                    float* __restrict__ C) {
    extern __shared__ __align__(128) char smem[];
    const uint32_t sbase = smem_u32(smem);
    const int tid = threadIdx.x;
    const int n0 = blockIdx.x * BN;
    const int m0 = blockIdx.y * BM;

    float acc[4][4][4];
#pragma unroll
    for (int i = 0; i < 4; i++)
#pragma unroll
        for (int j = 0; j < 4; j++)
#pragma unroll
            for (int e = 0; e < 4; e++) acc[i][j][e] = 0.0f;

    gemm_mainloop(sbase, tid,
                  Ahi + (size_t)m0 * GK, Alo + (size_t)m0 * GK,
                  Bhi + (size_t)n0 * GK, Blo + (size_t)n0 * GK, acc);

    const int lane = tid & 31;
    const int warp = tid >> 5;
    const int warp_m = warp >> 2;
    const int warp_n = warp & 3;
    const int er = lane >> 2;
    const int ec = (lane & 3) * 2;
#pragma unroll
    for (int mt = 0; mt < 4; mt++) {
        const int row = m0 + warp_m * 64 + mt * 16 + er;
#pragma unroll
        for (int nt = 0; nt < 4; nt++) {
            const int col = n0 + warp_n * 32 + nt * 8 + ec;
            *(float2*)&C[(size_t)row * C_DIM + col] = make_float2(acc[mt][nt][0], acc[mt][nt][1]);
            *(float2*)&C[(size_t)(row + 8) * C_DIM + col] = make_float2(acc[mt][nt][2], acc[mt][nt][3]);
        }
    }
}

// ---------------------------------------------------------------------------
// Banded causal attention on tensor cores (bf16 hi/lo, 3-pass).
// Block = (head, 64-query tile), 256 threads (2x4 warps).
// Keys j in [0,192) -> global jg = t0 - 128 + j.
// Phase A: S = Q@K^T  (M=64, N=192, K=64), warp tile 32x48.
// Softmax fp32 in smem; P -> bf16 hi/lo (overlaying S region).
// Phase B: O = P@V    (M=64, N=64, K=192), warp tile 32x16, V via ldmatrix.trans.
// ---------------------------------------------------------------------------
#define AROW 144          // 128B data + 16B pad per Q/K/V smem row
#define SROW 200          // floats per S row (192 data + 8 pad)
#define PROWB 400         // bytes per P row (384 data + 16 pad)

#define OFF_QH 0
#define OFF_QL 9216
#define OFF_KH 18432
#define OFF_KL 46080
#define OFF_VH 73728
#define OFF_VL 101376
#define OFF_SP 129024
#define ATTN_SMEM 180224

__global__ __launch_bounds__(256, 1) void attn_mma(const bf16* __restrict__ qhi,
                                                   const bf16* __restrict__ qlo,
                                                   const bf16* __restrict__ khi,
                                                   const bf16* __restrict__ klo,
                                                   const bf16* __restrict__ vhi,
                                                   const bf16* __restrict__ vlo,
                                                   bf16* __restrict__ yhi,
                                                   bf16* __restrict__ ylo) {
    extern __shared__ __align__(128) char smem[];
    const uint32_t sbase = smem_u32(smem);
    const int h   = blockIdx.y;
    const int t0  = blockIdx.x * 64;
    const int tid = threadIdx.x;
    const int hoff = h * DHEAD;

    // ---- stage Q/K/V hi+lo into padded smem via cp.async ----
    for (int idx = tid; idx < 512; idx += 256) {
        int row = idx >> 3, c = idx & 7;
        size_t src = (size_t)(t0 + row) * C_DIM + hoff + c * 8;
        uint32_t d = row * AROW + c * 16;
        cp16(sbase + OFF_QH + d, qhi + src);
        cp16(sbase + OFF_QL + d, qlo + src);
    }
    for (int idx = tid; idx < 1536; idx += 256) {
        int row = idx >> 3, c = idx & 7;
        int jg = t0 - BANDW + row;
        uint32_t d = row * AROW + c * 16;
        if (jg >= 0) {
            size_t src = (size_t)jg * C_DIM + hoff + c * 8;
            cp16(sbase + OFF_KH + d, khi + src);
            cp16(sbase + OFF_KL + d, klo + src);
            cp16(sbase + OFF_VH + d, vhi + src);
            cp16(sbase + OFF_VL + d, vlo + src);
        } else {
            stz16(sbase + OFF_KH + d);
            stz16(sbase + OFF_KL + d);
            stz16(sbase + OFF_VH + d);
            stz16(sbase + OFF_VL + d);
        }
    }
    cp_commit();
    asm volatile("cp.async.wait_group 0;" ::: "memory");
    __syncthreads();

    const int lane = tid & 31;
    const int warp = tid >> 5;
    const int wm = warp >> 2;       // 0..1
    const int wn = warp & 3;        // 0..3
    const int sel = lane >> 3;
    const int l7  = lane & 7;

    float* Sf = (float*)(smem + OFF_SP);

    // ---- Phase A: S = Q@K^T ----
    {
        const uint32_t aoff = (uint32_t)((wm * 32 + (sel & 1) * 8 + l7) * AROW + (sel >> 1) * 16);
        const uint32_t boff = (uint32_t)((wn * 48 + (sel >> 1) * 8 + l7) * AROW + (sel & 1) * 16);
        const uint32_t sQh = sbase + OFF_QH + aoff, sQl = sbase + OFF_QL + aoff;
        const uint32_t sKh = sbase + OFF_KH + boff, sKl = sbase + OFF_KL + boff;

        float acc[2][6][4];
#pragma unroll
        for (int i = 0; i < 2; i++)
#pragma unroll
            for (int j = 0; j < 6; j++)
#pragma unroll
                for (int e = 0; e < 4; e++) acc[i][j][e] = 0.0f;

#pragma unroll
        for (int ks = 0; ks < 4; ks++) {
            const uint32_t ka = ks * 32;
            uint32_t Ah[2][4], Al[2][4], Bh[6][2], Bl[6][2];
#pragma unroll
            for (int mt = 0; mt < 2; mt++) {
                ldm_x4(Ah[mt], sQh + mt * (16 * AROW) + ka);
                ldm_x4(Al[mt], sQl + mt * (16 * AROW) + ka);
            }
#pragma unroll
            for (int p = 0; p < 3; p++) {
                uint32_t rh[4], rl[4];
                ldm_x4(rh, sKh + p * (16 * AROW) + ka);
                ldm_x4(rl, sKl + p * (16 * AROW) + ka);
                Bh[2 * p][0] = rh[0]; Bh[2 * p][1] = rh[1];
                Bh[2 * p + 1][0] = rh[2]; Bh[2 * p + 1][1] = rh[3];
                Bl[2 * p][0] = rl[0]; Bl[2 * p][1] = rl[1];
                Bl[2 * p + 1][0] = rl[2]; Bl[2 * p + 1][1] = rl[3];
            }
#pragma unroll
            for (int mt = 0; mt < 2; mt++)
#pragma unroll
                for (int nt = 0; nt < 6; nt++) {
                    mma16816(acc[mt][nt], Ah[mt], Bh[nt]);
                    mma16816(acc[mt][nt], Ah[mt], Bl[nt]);
                    mma16816(acc[mt][nt], Al[mt], Bh[nt]);
                }
        }
        // store S (fp32, stride SROW)
        const int er = lane >> 2;
        const int ec = (lane & 3) * 2;
#pragma unroll
        for (int mt = 0; mt < 2; mt++) {
            const int row = wm * 32 + mt * 16 + er;
#pragma unroll
            for (int nt = 0; nt < 6; nt++) {
                const int col = wn * 48 + nt * 8 + ec;
                *(float2*)&Sf[row * SROW + col] = make_float2(acc[mt][nt][0], acc[mt][nt][1]);
                *(float2*)&Sf[(row + 8) * SROW + col] = make_float2(acc[mt][nt][2], acc[mt][nt][3]);
            }
        }
    }
    __syncthreads();

    // ---- softmax (4 lanes per row, contiguous 48-j blocks) ----
    {
        const int qi  = tid >> 2;
        const int sub = tid & 3;
        const int i   = t0 + qi;
        const int j0  = sub * 48;
        float s[48];
        const float4* Srow = (const float4*)(Sf + qi * SROW + j0);
#pragma unroll
        for (int n4 = 0; n4 < 12; n4++) {
            float4 v = Srow[n4];
            s[4 * n4] = v.x; s[4 * n4 + 1] = v.y; s[4 * n4 + 2] = v.z; s[4 * n4 + 3] = v.w;
        }
        float mx = -1e30f;
#pragma unroll
        for (int n = 0; n < 48; n++) {
            int jg = t0 - BANDW + j0 + n;
            bool valid = (jg >= 0) && (jg <= i) && ((i - jg) < BANDW);
            s[n] = valid ? s[n] * 0.125f : -1e30f;
            mx = fmaxf(mx, s[n]);
        }
        mx = fmaxf(mx, __shfl_xor_sync(0xFFFFFFFFu, mx, 1));
        mx = fmaxf(mx, __shfl_xor_sync(0xFFFFFFFFu, mx, 2));
        float sum = 0.0f;
#pragma unroll
        for (int n = 0; n < 48; n++) { s[n] = __expf(s[n] - mx); sum += s[n]; }
        sum += __shfl_xor_sync(0xFFFFFFFFu, sum, 1);
        sum += __shfl_xor_sync(0xFFFFFFFFu, sum, 2);
        float inv = 1.0f / sum;

        __syncthreads();   // all S reads complete before P overwrites the region

        char* Pb = smem + OFF_SP;
        bf162* PhiRow = (bf162*)(Pb + qi * PROWB + j0 * 2);
        bf162* PloRow = (bf162*)(Pb + 25600 + qi * PROWB + j0 * 2);
#pragma unroll
        for (int n2 = 0; n2 < 24; n2++) {
            float p0 = s[2 * n2] * inv, p1 = s[2 * n2 + 1] * inv;
            bf16 h0, h1, l0, l1;
            split2(p0, h0, l0); split2(p1, h1, l1);
            PhiRow[n2] = bf162(h0, h1);
            PloRow[n2] = bf162(l0, l1);
        }
    }
    __syncthreads();

    // ---- Phase B: O = P@V ----
    {
        const uint32_t aoff = (uint32_t)((wm * 32 + (sel & 1) * 8 + l7) * PROWB + (sel >> 1) * 16);
        const uint32_t voff = (uint32_t)(((sel & 1) * 8 + l7) * AROW + (sel >> 1) * 16 + wn * 32);
        const uint32_t sPh = sbase + OFF_SP + aoff;
        const uint32_t sPl = sbase + OFF_SP + 25600 + aoff;
        const uint32_t sVh = sbase + OFF_VH + voff;
        const uint32_t sVl = sbase + OFF_VL + voff;

        float acc[2][2][4];
#pragma unroll
        for (int i = 0; i < 2; i++)
#pragma unroll
            for (int j = 0; j < 2; j++)
#pragma unroll
                for (int e = 0; e < 4; e++) acc[i][j][e] = 0.0f;

#pragma unroll
        for (int ks = 0; ks < 12; ks++) {
            uint32_t Ph[2][4], Pl[2][4], Vh[2][2], Vl[2][2];
#pragma unroll
            for (int mt = 0; mt < 2; mt++) {
                ldm_x4(Ph[mt], sPh + mt * (16 * PROWB) + ks * 32);
                ldm_x4(Pl[mt], sPl + mt * (16 * PROWB) + ks * 32);
            }
            {
                uint32_t rh[4], rl[4];
                ldm_x4t(rh, sVh + ks * (16 * AROW));
                ldm_x4t(rl, sVl + ks * (16 * AROW));
                Vh[0][0] = rh[0]; Vh[0][1] = rh[1]; Vh[1][0] = rh[2]; Vh[1][1] = rh[3];
                Vl[0][0] = rl[0]; Vl[0][1] = rl[1]; Vl[1][0] = rl[2]; Vl[1][1] = rl[3];
            }
#pragma unroll
            for (int mt = 0; mt < 2; mt++)
#pragma unroll
                for (int nt = 0; nt < 2; nt++) {
                    mma16816(acc[mt][nt], Ph[mt], Vh[nt]);
                    mma16816(acc[mt][nt], Ph[mt], Vl[nt]);
                    mma16816(acc[mt][nt], Pl[mt], Vh[nt]);
                }
        }

        // epilogue: write y as bf16 hi/lo
        const int er = lane >> 2;
        const int ec = (lane & 3) * 2;
#pragma unroll
        for (int mt = 0; mt < 2; mt++) {
            const int row = wm * 32 + mt * 16 + er;
#pragma unroll
            for (int nt = 0; nt < 2; nt++) {
                const int col = wn * 16 + nt * 8 + ec;
#pragma unroll
                for (int hh = 0; hh < 2; hh++) {
                    float c0 = acc[mt][nt][2 * hh], c1 = acc[mt][nt][2 * hh + 1];
                    bf16 h0, h1, l0, l1;
                    split2(c0, h0, l0); split2(c1, h1, l1);
                    size_t off = (size_t)(t0 + row + 8 * hh) * C_DIM + hoff + col;
                    *(bf162*)&yhi[off] = bf162(h0, h1);
                    *(bf162*)&ylo[off] = bf162(l0, l1);
                }
            }
        }
    }
}

// ---------------------------------------------------------------------------
extern "C" void kernel_launch(void* const* d_in, const int* in_sizes, int n_in,
                              void* d_out, int out_size) {
    const float* x  = (const float*)d_in[0];
    const float* Wq = (const float*)d_in[1];
    const float* Wk = (const float*)d_in[2];
    const float* Wv = (const float*)d_in[3];
    const float* Wo = (const float*)d_in[4];
    float* out = (float*)d_out;

    bf16 *xhi, *xlo, *qhi, *qlo, *khi, *klo, *vhi, *vlo, *ahi, *alo, *whi, *wlo;
    cudaGetSymbolAddress((void**)&xhi, g_xhi);
    cudaGetSymbolAddress((void**)&xlo, g_xlo);
    cudaGetSymbolAddress((void**)&qhi, g_qhi);
    cudaGetSymbolAddress((void**)&qlo, g_qlo);
    cudaGetSymbolAddress((void**)&khi, g_khi);
    cudaGetSymbolAddress((void**)&klo, g_klo);
    cudaGetSymbolAddress((void**)&vhi, g_vhi);
    cudaGetSymbolAddress((void**)&vlo, g_vlo);
    cudaGetSymbolAddress((void**)&ahi, g_ahi);
    cudaGetSymbolAddress((void**)&alo, g_alo);
    cudaGetSymbolAddress((void**)&whi, g_whi);
    cudaGetSymbolAddress((void**)&wlo, g_wlo);

    cudaFuncSetAttribute(mma_gemm_qkv, cudaFuncAttributeMaxDynamicSharedMemorySize, GEMM_SMEM);
    cudaFuncSetAttribute(mma_gemm_f32, cudaFuncAttributeMaxDynamicSharedMemorySize, GEMM_SMEM);
    cudaFuncSetAttribute(attn_mma, cudaFuncAttributeMaxDynamicSharedMemorySize, ATTN_SMEM);

    const int NX4 = T_SEQ * C_DIM / 4;
    const int NW4 = C_DIM * C_DIM / 4;
    const size_t WSZ = (size_t)C_DIM * C_DIM;

    split_kernel<<<(NX4 + 255) / 256, 256>>>(x, xhi, xlo, NX4);
    split_w4_kernel<<<dim3((NW4 + 255) / 256, 4), 256>>>(Wq, Wk, Wv, Wo, whi, wlo, NW4);

    mma_gemm_qkv<<<dim3(24, 32), 256, GEMM_SMEM>>>(xhi, xlo, whi, wlo,
                                                   qhi, qlo, khi, klo, vhi, vlo);

    attn_mma<<<dim3(T_SEQ / 64, NH), 256, ATTN_SMEM>>>(qhi, qlo, khi, klo, vhi, vlo, ahi, alo);

    mma_gemm_f32<<<dim3(8, 32), 256, GEMM_SMEM>>>(ahi, alo, whi + 3 * WSZ, wlo + 3 * WSZ, out);
}